// round 1
// baseline (speedup 1.0000x reference)
#include <cuda_runtime.h>
#include <math.h>

// Problem dims
#define Dm   1024
#define Sseq 1024
#define Bb   2
#define Hh   16
#define DHh  64
#define Ee   8
#define Gg   2
#define Vv   4096
#define TOK  (Bb*Sseq)     // 2048 tokens
#define EPSV 1e-5f

// ---------------- device scratch (static allocation is the sanctioned path) ----
__device__ float g_q[TOK*Dm];
__device__ float g_k[TOK*Dm];
__device__ float g_v[TOK*Dm];
__device__ float g_attn[TOK*Dm];
__device__ float g_proj[TOK*Dm];
__device__ float g_normed[TOK*Dm];
__device__ float g_scores[(size_t)Bb*Hh*Sseq*Sseq];   // 128 MB
__device__ float g_h[(size_t)Ee*TOK*Vv];              // 256 MB
__device__ float g_eo[(size_t)Ee*TOK*Dm];             // 64 MB
__device__ float g_coef[TOK*Ee];

// ---------------- helpers -----------------------------------------------------
__device__ __forceinline__ float block_sum256(float v, float* red) {
    #pragma unroll
    for (int o = 16; o > 0; o >>= 1) v += __shfl_xor_sync(0xffffffffu, v, o);
    if ((threadIdx.x & 31) == 0) red[threadIdx.x >> 5] = v;
    __syncthreads();
    float s = red[0];
    #pragma unroll
    for (int i = 1; i < 8; i++) s += red[i];
    __syncthreads();   // allow red reuse
    return s;
}

// ---------------- generic FP32 GEMM: C[M,N] = A[M,K] @ W[K,N] + bias ----------
// 128x128 block tile, K-step 8, 256 threads, 8x8 per-thread microtile.
template<bool RELU>
__global__ __launch_bounds__(256) void sgemm128(
    const float* __restrict__ A, const float* __restrict__ W,
    const float* __restrict__ bias, float* __restrict__ C,
    int M, int N, int K)
{
    __shared__ float As[8][132];
    __shared__ float Bs[8][132];
    const int t  = threadIdx.x;
    const int tx = t & 15, ty = t >> 4;
    const int n0 = blockIdx.x * 128, m0 = blockIdx.y * 128;
    const int am = t >> 1, ak = (t & 1) * 4;     // A load: row am, 4 k's
    const int bk = t >> 5, bn = (t & 31) * 4;    // W load: row bk, 4 n's
    const float* Ap = A + (size_t)(m0 + am) * K + ak;
    const float* Wp = W + (size_t)bk * N + n0 + bn;

    float acc[8][8];
    #pragma unroll
    for (int i = 0; i < 8; i++)
        #pragma unroll
        for (int j = 0; j < 8; j++) acc[i][j] = 0.f;

    for (int k0 = 0; k0 < K; k0 += 8) {
        float4 av = *(const float4*)(Ap + k0);
        float4 wv = *(const float4*)(Wp + (size_t)k0 * N);
        As[ak+0][am] = av.x; As[ak+1][am] = av.y;
        As[ak+2][am] = av.z; As[ak+3][am] = av.w;
        *(float4*)&Bs[bk][bn] = wv;
        __syncthreads();
        #pragma unroll
        for (int kk = 0; kk < 8; kk++) {
            float4 a0 = *(const float4*)&As[kk][ty*8];
            float4 a1 = *(const float4*)&As[kk][ty*8+4];
            float4 b0 = *(const float4*)&Bs[kk][tx*8];
            float4 b1 = *(const float4*)&Bs[kk][tx*8+4];
            float a[8] = {a0.x,a0.y,a0.z,a0.w,a1.x,a1.y,a1.z,a1.w};
            float b[8] = {b0.x,b0.y,b0.z,b0.w,b1.x,b1.y,b1.z,b1.w};
            #pragma unroll
            for (int i = 0; i < 8; i++)
                #pragma unroll
                for (int j = 0; j < 8; j++)
                    acc[i][j] = fmaf(a[i], b[j], acc[i][j]);
        }
        __syncthreads();
    }

    float bb[8];
    #pragma unroll
    for (int j = 0; j < 8; j++) bb[j] = bias[n0 + tx*8 + j];
    #pragma unroll
    for (int i = 0; i < 8; i++) {
        float o[8];
        #pragma unroll
        for (int j = 0; j < 8; j++) {
            float vv = acc[i][j] + bb[j];
            o[j] = RELU ? fmaxf(vv, 0.f) : vv;
        }
        float* cp = C + (size_t)(m0 + ty*8 + i) * N + n0 + tx*8;
        ((float4*)cp)[0] = make_float4(o[0], o[1], o[2], o[3]);
        ((float4*)cp)[1] = make_float4(o[4], o[5], o[6], o[7]);
    }
}

// ---------------- attention: scores[bh][q][k] = (q . k) / 8 -------------------
__global__ __launch_bounds__(256) void attn_scores(
    const float* __restrict__ q, const float* __restrict__ k,
    float* __restrict__ scr)
{
    __shared__ float Qs[64][68];   // [dh][q]
    __shared__ float Ks[64][68];   // [dh][k]
    const int t  = threadIdx.x;
    const int tx = t & 15, ty = t >> 4;
    const int k0 = blockIdx.x * 64, q0 = blockIdx.y * 64;
    const int bh = blockIdx.z, b = bh >> 4, h = bh & 15;
    const size_t qbase = (size_t)(b*Sseq + q0) * Dm + h*64;
    const size_t kbase = (size_t)(b*Sseq + k0) * Dm + h*64;

    #pragma unroll
    for (int i = 0; i < 4; i++) {
        int f = t + 256*i;
        int row = f >> 4, c4 = (f & 15) * 4;
        float4 qv = *(const float4*)(q + qbase + (size_t)row*Dm + c4);
        float4 kv = *(const float4*)(k + kbase + (size_t)row*Dm + c4);
        Qs[c4+0][row]=qv.x; Qs[c4+1][row]=qv.y; Qs[c4+2][row]=qv.z; Qs[c4+3][row]=qv.w;
        Ks[c4+0][row]=kv.x; Ks[c4+1][row]=kv.y; Ks[c4+2][row]=kv.z; Ks[c4+3][row]=kv.w;
    }
    __syncthreads();

    float acc[4][4] = {};
    #pragma unroll 8
    for (int dh = 0; dh < 64; dh++) {
        float4 a  = *(const float4*)&Qs[dh][ty*4];
        float4 bv = *(const float4*)&Ks[dh][tx*4];
        float aa[4] = {a.x,a.y,a.z,a.w}, bbv[4] = {bv.x,bv.y,bv.z,bv.w};
        #pragma unroll
        for (int i = 0; i < 4; i++)
            #pragma unroll
            for (int j = 0; j < 4; j++)
                acc[i][j] = fmaf(aa[i], bbv[j], acc[i][j]);
    }
    const float scale = 0.125f;  // 1/sqrt(64)
    size_t obase = (size_t)bh*Sseq*Sseq + (size_t)q0*Sseq + k0;
    #pragma unroll
    for (int i = 0; i < 4; i++) {
        float4 o = make_float4(acc[i][0]*scale, acc[i][1]*scale,
                               acc[i][2]*scale, acc[i][3]*scale);
        *(float4*)(scr + obase + (size_t)(ty*4+i)*Sseq + tx*4) = o;
    }
}

// ---------------- row softmax over 1024 columns -------------------------------
__global__ __launch_bounds__(256) void softmax_rows(float* __restrict__ scr)
{
    __shared__ float red[8];
    const int t = threadIdx.x;
    float4* row = (float4*)(scr + (size_t)blockIdx.x * 1024);
    float4 v = row[t];
    float m = fmaxf(fmaxf(v.x, v.y), fmaxf(v.z, v.w));
    #pragma unroll
    for (int o = 16; o > 0; o >>= 1) m = fmaxf(m, __shfl_xor_sync(0xffffffffu, m, o));
    if ((t & 31) == 0) red[t >> 5] = m;
    __syncthreads();
    float mm = red[0];
    #pragma unroll
    for (int i = 1; i < 8; i++) mm = fmaxf(mm, red[i]);
    __syncthreads();
    v.x = __expf(v.x - mm); v.y = __expf(v.y - mm);
    v.z = __expf(v.z - mm); v.w = __expf(v.w - mm);
    float s = v.x + v.y + v.z + v.w;
    #pragma unroll
    for (int o = 16; o > 0; o >>= 1) s += __shfl_xor_sync(0xffffffffu, s, o);
    if ((t & 31) == 0) red[t >> 5] = s;
    __syncthreads();
    float ss = red[0];
    #pragma unroll
    for (int i = 1; i < 8; i++) ss += red[i];
    float inv = 1.f / ss;
    v.x *= inv; v.y *= inv; v.z *= inv; v.w *= inv;
    row[t] = v;
}

// ---------------- PV: out[b,q,h,dh] = sum_k P[bh,q,k] V[b,k,h,dh] -------------
__global__ __launch_bounds__(256) void attn_pv(
    const float* __restrict__ scr, const float* __restrict__ v,
    float* __restrict__ out)
{
    __shared__ float Ps[64][68];   // [k][q]
    __shared__ float Vs[64][68];   // [k][dh]
    const int t  = threadIdx.x;
    const int tx = t & 15, ty = t >> 4;
    const int q0 = blockIdx.x * 64;
    const int bh = blockIdx.y, b = bh >> 4, h = bh & 15;

    float acc[4][4] = {};
    for (int kt = 0; kt < 16; kt++) {
        #pragma unroll
        for (int i = 0; i < 4; i++) {
            int f = t + 256*i;
            int r = f >> 4, c4 = (f & 15) * 4;
            float4 pv = *(const float4*)(scr + (size_t)bh*Sseq*Sseq
                                         + (size_t)(q0+r)*Sseq + kt*64 + c4);
            Ps[c4+0][r]=pv.x; Ps[c4+1][r]=pv.y; Ps[c4+2][r]=pv.z; Ps[c4+3][r]=pv.w;
            float4 vv = *(const float4*)(v + ((size_t)(b*Sseq) + kt*64 + r)*Dm + h*64 + c4);
            *(float4*)&Vs[r][c4] = vv;
        }
        __syncthreads();
        #pragma unroll 8
        for (int kk = 0; kk < 64; kk++) {
            float4 a  = *(const float4*)&Ps[kk][ty*4];
            float4 bv = *(const float4*)&Vs[kk][tx*4];
            float aa[4] = {a.x,a.y,a.z,a.w}, bbv[4] = {bv.x,bv.y,bv.z,bv.w};
            #pragma unroll
            for (int i = 0; i < 4; i++)
                #pragma unroll
                for (int j = 0; j < 4; j++)
                    acc[i][j] = fmaf(aa[i], bbv[j], acc[i][j]);
        }
        __syncthreads();
    }
    #pragma unroll
    for (int i = 0; i < 4; i++) {
        float4 o = make_float4(acc[i][0], acc[i][1], acc[i][2], acc[i][3]);
        *(float4*)(out + ((size_t)(b*Sseq) + q0 + ty*4 + i)*Dm + h*64 + tx*4) = o;
    }
}

// ---------------- residual add + layernorm ------------------------------------
__global__ __launch_bounds__(256) void add_ln(
    const float* __restrict__ a, const float* __restrict__ b,
    const float* __restrict__ gamma, const float* __restrict__ beta,
    float* __restrict__ out)
{
    __shared__ float red[8];
    const int t = threadIdx.x;
    const size_t base = (size_t)blockIdx.x * Dm;
    float4 va = ((const float4*)(a + base))[t];
    float4 vb = ((const float4*)(b + base))[t];
    float4 s = make_float4(va.x+vb.x, va.y+vb.y, va.z+vb.z, va.w+vb.w);
    float tot = block_sum256(s.x + s.y + s.z + s.w, red);
    float mu = tot * (1.f / Dm);
    float lq = (s.x-mu)*(s.x-mu) + (s.y-mu)*(s.y-mu)
             + (s.z-mu)*(s.z-mu) + (s.w-mu)*(s.w-mu);
    float var = block_sum256(lq, red) * (1.f / Dm);
    float rstd = rsqrtf(var + EPSV);
    float4 gg = ((const float4*)gamma)[t];
    float4 bt = ((const float4*)beta)[t];
    float4 o;
    o.x = (s.x - mu) * rstd * gg.x + bt.x;
    o.y = (s.y - mu) * rstd * gg.y + bt.y;
    o.z = (s.z - mu) * rstd * gg.z + bt.z;
    o.w = (s.w - mu) * rstd * gg.w + bt.w;
    ((float4*)(out + base))[t] = o;
}

// ---------------- gate: coef[t,e] = sum_g softmax_e(x . gw[g,:,e]) / G --------
__global__ __launch_bounds__(256) void gate_coef(
    const float* __restrict__ xn, const float* __restrict__ gw,
    float* __restrict__ coef)
{
    __shared__ float red[16][9];
    const int t = threadIdx.x, tkn = blockIdx.x;
    float acc[16];
    #pragma unroll
    for (int ge = 0; ge < 16; ge++) acc[ge] = 0.f;
    for (int d = t; d < Dm; d += 256) {
        float xv = xn[(size_t)tkn*Dm + d];
        #pragma unroll
        for (int ge = 0; ge < 16; ge++)
            acc[ge] = fmaf(xv, gw[(size_t)(ge >> 3)*Dm*Ee + (size_t)d*Ee + (ge & 7)], acc[ge]);
    }
    #pragma unroll
    for (int ge = 0; ge < 16; ge++) {
        float v = acc[ge];
        #pragma unroll
        for (int o = 16; o > 0; o >>= 1) v += __shfl_xor_sync(0xffffffffu, v, o);
        if ((t & 31) == 0) red[ge][t >> 5] = v;
    }
    __syncthreads();
    if (t == 0) {
        float logits[16];
        #pragma unroll
        for (int ge = 0; ge < 16; ge++) {
            float s = 0.f;
            #pragma unroll
            for (int w = 0; w < 8; w++) s += red[ge][w];
            logits[ge] = s;
        }
        float c[8];
        #pragma unroll
        for (int e = 0; e < 8; e++) c[e] = 0.f;
        #pragma unroll
        for (int g = 0; g < 2; g++) {
            float m = logits[g*8];
            #pragma unroll
            for (int e = 1; e < 8; e++) m = fmaxf(m, logits[g*8+e]);
            float s = 0.f, pe[8];
            #pragma unroll
            for (int e = 0; e < 8; e++) { pe[e] = __expf(logits[g*8+e] - m); s += pe[e]; }
            float inv = 1.f / s;
            #pragma unroll
            for (int e = 0; e < 8; e++) c[e] += pe[e] * inv;
        }
        #pragma unroll
        for (int e = 0; e < 8; e++) coef[(size_t)tkn*8 + e] = c[e] * 0.5f;  // /G
    }
}

// ---------------- combine experts + residual + layernorm ----------------------
__global__ __launch_bounds__(256) void combine_ln(
    const float* __restrict__ eo, const float* __restrict__ coef,
    const float* __restrict__ xn,
    const float* __restrict__ gamma, const float* __restrict__ beta,
    float* __restrict__ out)
{
    __shared__ float red[8];
    __shared__ float cf[8];
    const int t = threadIdx.x, tkn = blockIdx.x;
    if (t < 8) cf[t] = coef[(size_t)tkn*8 + t];
    __syncthreads();
    const size_t base = (size_t)tkn * Dm;
    float4 s = ((const float4*)(xn + base))[t];
    #pragma unroll
    for (int e = 0; e < 8; e++) {
        float4 v = ((const float4*)(eo + ((size_t)e*TOK + tkn)*Dm))[t];
        float c = cf[e];
        s.x = fmaf(c, v.x, s.x); s.y = fmaf(c, v.y, s.y);
        s.z = fmaf(c, v.z, s.z); s.w = fmaf(c, v.w, s.w);
    }
    float tot = block_sum256(s.x + s.y + s.z + s.w, red);
    float mu = tot * (1.f / Dm);
    float lq = (s.x-mu)*(s.x-mu) + (s.y-mu)*(s.y-mu)
             + (s.z-mu)*(s.z-mu) + (s.w-mu)*(s.w-mu);
    float var = block_sum256(lq, red) * (1.f / Dm);
    float rstd = rsqrtf(var + EPSV);
    float4 gg = ((const float4*)gamma)[t];
    float4 bt = ((const float4*)beta)[t];
    float4 o;
    o.x = (s.x - mu) * rstd * gg.x + bt.x;
    o.y = (s.y - mu) * rstd * gg.y + bt.y;
    o.z = (s.z - mu) * rstd * gg.z + bt.z;
    o.w = (s.w - mu) * rstd * gg.w + bt.w;
    ((float4*)(out + base))[t] = o;
}

// ---------------- launch -------------------------------------------------------
extern "C" void kernel_launch(void* const* d_in, const int* in_sizes, int n_in,
                              void* d_out, int out_size)
{
    const float* x     = (const float*)d_in[0];
    const float* wq    = (const float*)d_in[1];
    const float* bq    = (const float*)d_in[2];
    const float* wk    = (const float*)d_in[3];
    const float* bk    = (const float*)d_in[4];
    const float* wv    = (const float*)d_in[5];
    const float* bv    = (const float*)d_in[6];
    const float* wo    = (const float*)d_in[7];
    const float* bo    = (const float*)d_in[8];
    const float* ln1g  = (const float*)d_in[9];
    const float* ln1b  = (const float*)d_in[10];
    const float* ln2g  = (const float*)d_in[11];
    const float* ln2b  = (const float*)d_in[12];
    const float* gatew = (const float*)d_in[13];
    const float* ew1   = (const float*)d_in[14];
    const float* eb1   = (const float*)d_in[15];
    const float* ew2   = (const float*)d_in[16];
    const float* eb2   = (const float*)d_in[17];
    float* out = (float*)d_out;

    float *q, *k, *v, *attn, *proj, *normed, *scores, *h, *eo, *coef;
    cudaGetSymbolAddress((void**)&q,      g_q);
    cudaGetSymbolAddress((void**)&k,      g_k);
    cudaGetSymbolAddress((void**)&v,      g_v);
    cudaGetSymbolAddress((void**)&attn,   g_attn);
    cudaGetSymbolAddress((void**)&proj,   g_proj);
    cudaGetSymbolAddress((void**)&normed, g_normed);
    cudaGetSymbolAddress((void**)&scores, g_scores);
    cudaGetSymbolAddress((void**)&h,      g_h);
    cudaGetSymbolAddress((void**)&eo,     g_eo);
    cudaGetSymbolAddress((void**)&coef,   g_coef);

    dim3 blk(256);

    // QKV projections
    sgemm128<false><<<dim3(8, 16), blk>>>(x, wq, bq, q, TOK, Dm, Dm);
    sgemm128<false><<<dim3(8, 16), blk>>>(x, wk, bk, k, TOK, Dm, Dm);
    sgemm128<false><<<dim3(8, 16), blk>>>(x, wv, bv, v, TOK, Dm, Dm);

    // attention
    attn_scores<<<dim3(16, 16, 32), blk>>>(q, k, scores);
    softmax_rows<<<Bb*Hh*Sseq, blk>>>(scores);
    attn_pv<<<dim3(16, 32), blk>>>(scores, v, attn);

    // output projection + residual + LN1
    sgemm128<false><<<dim3(8, 16), blk>>>(attn, wo, bo, proj, TOK, Dm, Dm);
    add_ln<<<TOK, blk>>>(proj, x, ln1g, ln1b, normed);

    // MoE
    gate_coef<<<TOK, blk>>>(normed, gatew, coef);
    for (int e = 0; e < Ee; e++)
        sgemm128<true><<<dim3(32, 16), blk>>>(
            normed, ew1 + (size_t)e*Dm*Vv, eb1 + (size_t)e*Vv,
            h + (size_t)e*TOK*Vv, TOK, Vv, Dm);
    for (int e = 0; e < Ee; e++)
        sgemm128<false><<<dim3(8, 16), blk>>>(
            h + (size_t)e*TOK*Vv, ew2 + (size_t)e*Vv*Dm, eb2 + (size_t)e*Dm,
            eo + (size_t)e*TOK*Dm, TOK, Dm, Vv);

    // combine + residual + LN2 -> output
    combine_ln<<<TOK, blk>>>(eo, coef, normed, ln2g, ln2b, out);
}

// round 4
// speedup vs baseline: 5.7505x; 5.7505x over previous
#include <cuda_runtime.h>
#include <math.h>
#include <stdint.h>

// Problem dims
#define Dm   1024
#define Sseq 1024
#define Bb   2
#define Hh   16
#define Ee   8
#define Vv   4096
#define TOK  (Bb*Sseq)
#define EPSV 1e-5f

// ---------------- device scratch ------------------------------------------------
__device__ float g_q[TOK*Dm];
__device__ float g_k[TOK*Dm];
__device__ float g_v[TOK*Dm];
__device__ float g_attn[TOK*Dm];
__device__ float g_proj[TOK*Dm];
__device__ float g_normed[TOK*Dm];
__device__ float g_scores[(size_t)Bb*Hh*Sseq*Sseq];
__device__ float g_h[(size_t)Ee*TOK*Vv];
__device__ float g_eo[(size_t)Ee*TOK*Dm];
__device__ float g_coef[TOK*Ee];
// transposed weights (N-major: Wt[n][k])
__device__ float g_wqt[Dm*Dm];
__device__ float g_wkt[Dm*Dm];
__device__ float g_wvt[Dm*Dm];
__device__ float g_wot[Dm*Dm];
__device__ float g_w1t[(size_t)Ee*Vv*Dm];
__device__ float g_w2t[(size_t)Ee*Dm*Vv];

// ---------------- helpers -------------------------------------------------------
__device__ __forceinline__ uint32_t f2tf(float f) {
    uint32_t u; asm("cvt.rna.tf32.f32 %0, %1;" : "=r"(u) : "f"(f)); return u;
}
__device__ __forceinline__ void mma_tf32(float* c, const uint32_t* a, const uint32_t* b) {
    asm volatile("mma.sync.aligned.m16n8k8.row.col.f32.tf32.tf32.f32 "
        "{%0,%1,%2,%3}, {%4,%5,%6,%7}, {%8,%9}, {%0,%1,%2,%3};"
        : "+f"(c[0]), "+f"(c[1]), "+f"(c[2]), "+f"(c[3])
        : "r"(a[0]), "r"(a[1]), "r"(a[2]), "r"(a[3]), "r"(b[0]), "r"(b[1]));
}

// SMEM geometry for mma_gemm: padded stride 36 words per 32-float row.
#define LDS_STRIDE 36
#define TILE_WORDS (128 * LDS_STRIDE)            // 4608 words per buffer
#define SMEM_GEMM_BYTES (4 * TILE_WORDS * 4 * 2) // A(2 bufs) + B(2 bufs) = 73728

// ---------------- tensor-core tf32 GEMM: C[M,N] = A[M,K] @ Bt[N,K]^T + bias -----
// 128x128 block tile, K-chunk 32, 256 threads (8 warps x 64x32 warp tile),
// double-buffered SMEM with register-staged prefetch.
template<bool RELU>
__global__ __launch_bounds__(256) void mma_gemm(
    const float* __restrict__ A, const float* __restrict__ Bt,
    const float* __restrict__ bias, float* __restrict__ C,
    int M, int N, int K,
    long long sA, long long sB, long long sBias, long long sC)
{
    extern __shared__ uint32_t sh[];
    uint32_t* Asm = sh;                    // [2][TILE_WORDS]
    uint32_t* Bsm = sh + 2 * TILE_WORDS;   // [2][TILE_WORDS]

    const int t = threadIdx.x;
    const int lane = t & 31, w = t >> 5;
    const int warp_m = w >> 2;             // 0..1
    const int warp_n = w & 3;              // 0..3
    const int lr = lane >> 2;              // 0..7
    const int lc = lane & 3;               // 0..3

    const int eb = blockIdx.z;
    A    += (size_t)eb * sA;
    Bt   += (size_t)eb * sB;
    bias += (size_t)eb * sBias;
    C    += (size_t)eb * sC;
    const int n0 = blockIdx.x * 128, m0 = blockIdx.y * 128;

    // global load mapping: thread covers rows r0+32*i, cols kc..kc+3 (i=0..3)
    const int kc = (t & 7) * 4;
    const int r0 = t >> 3;
    const float* Ag = A  + (size_t)(m0 + r0) * K + kc;
    const float* Bg = Bt + (size_t)(n0 + r0) * K + kc;
    const int sts_base = r0 * LDS_STRIDE + kc;

    float acc[4][4][4];
    #pragma unroll
    for (int mt = 0; mt < 4; mt++)
        #pragma unroll
        for (int nt = 0; nt < 4; nt++)
            #pragma unroll
            for (int i = 0; i < 4; i++) acc[mt][nt][i] = 0.f;

    const int nst = K >> 5;

    // stage 0 -> smem buf 0
    {
        float4 pa[4], pb[4];
        #pragma unroll
        for (int i = 0; i < 4; i++) {
            pa[i] = *(const float4*)(Ag + (size_t)(32 * i) * K);
            pb[i] = *(const float4*)(Bg + (size_t)(32 * i) * K);
        }
        #pragma unroll
        for (int i = 0; i < 4; i++) {
            uint32_t* da = Asm + sts_base + i * 32 * LDS_STRIDE;
            uint32_t* db = Bsm + sts_base + i * 32 * LDS_STRIDE;
            da[0] = f2tf(pa[i].x); da[1] = f2tf(pa[i].y);
            da[2] = f2tf(pa[i].z); da[3] = f2tf(pa[i].w);
            db[0] = f2tf(pb[i].x); db[1] = f2tf(pb[i].y);
            db[2] = f2tf(pb[i].z); db[3] = f2tf(pb[i].w);
        }
    }
    __syncthreads();

    const int a_off = (warp_m * 64 + lr) * LDS_STRIDE + lc;
    const int b_off = (warp_n * 32 + lr) * LDS_STRIDE + lc;

    for (int s = 0; s < nst; s++) {
        const int buf = s & 1;
        const bool more = (s + 1) < nst;
        float4 pa[4], pb[4];
        if (more) {
            const float* ag = Ag + (size_t)(32 * (s + 1));
            const float* bg = Bg + (size_t)(32 * (s + 1));
            #pragma unroll
            for (int i = 0; i < 4; i++) {
                pa[i] = *(const float4*)(ag + (size_t)(32 * i) * K);
                pb[i] = *(const float4*)(bg + (size_t)(32 * i) * K);
            }
        }

        const uint32_t* Apt = Asm + buf * TILE_WORDS + a_off;
        const uint32_t* Bpt = Bsm + buf * TILE_WORDS + b_off;
        #pragma unroll
        for (int kk = 0; kk < 4; kk++) {
            const int k = kk * 8;
            uint32_t af[4][4], bf[4][2];
            #pragma unroll
            for (int mt = 0; mt < 4; mt++) {
                af[mt][0] = Apt[(mt * 16    ) * LDS_STRIDE + k];
                af[mt][1] = Apt[(mt * 16 + 8) * LDS_STRIDE + k];
                af[mt][2] = Apt[(mt * 16    ) * LDS_STRIDE + k + 4];
                af[mt][3] = Apt[(mt * 16 + 8) * LDS_STRIDE + k + 4];
            }
            #pragma unroll
            for (int nt = 0; nt < 4; nt++) {
                bf[nt][0] = Bpt[(nt * 8) * LDS_STRIDE + k];
                bf[nt][1] = Bpt[(nt * 8) * LDS_STRIDE + k + 4];
            }
            #pragma unroll
            for (int mt = 0; mt < 4; mt++)
                #pragma unroll
                for (int nt = 0; nt < 4; nt++)
                    mma_tf32(acc[mt][nt], af[mt], bf[nt]);
        }

        if (more) {
            const int nb = (s + 1) & 1;
            #pragma unroll
            for (int i = 0; i < 4; i++) {
                uint32_t* da = Asm + nb * TILE_WORDS + sts_base + i * 32 * LDS_STRIDE;
                uint32_t* db = Bsm + nb * TILE_WORDS + sts_base + i * 32 * LDS_STRIDE;
                da[0] = f2tf(pa[i].x); da[1] = f2tf(pa[i].y);
                da[2] = f2tf(pa[i].z); da[3] = f2tf(pa[i].w);
                db[0] = f2tf(pb[i].x); db[1] = f2tf(pb[i].y);
                db[2] = f2tf(pb[i].z); db[3] = f2tf(pb[i].w);
            }
        }
        __syncthreads();
    }

    // epilogue: c0/c1 at (row, col..col+1), c2/c3 at (row+8, col..col+1)
    #pragma unroll
    for (int mt = 0; mt < 4; mt++) {
        const int m = m0 + warp_m * 64 + mt * 16 + lr;
        #pragma unroll
        for (int nt = 0; nt < 4; nt++) {
            const int n = n0 + warp_n * 32 + nt * 8 + lc * 2;
            const float b0 = bias[n], b1 = bias[n + 1];
            float o0 = acc[mt][nt][0] + b0, o1 = acc[mt][nt][1] + b1;
            float o2 = acc[mt][nt][2] + b0, o3 = acc[mt][nt][3] + b1;
            if (RELU) {
                o0 = fmaxf(o0, 0.f); o1 = fmaxf(o1, 0.f);
                o2 = fmaxf(o2, 0.f); o3 = fmaxf(o3, 0.f);
            }
            *(float2*)(C + (size_t)m * N + n)       = make_float2(o0, o1);
            *(float2*)(C + (size_t)(m + 8) * N + n) = make_float2(o2, o3);
        }
    }
}

// ---------------- weight transpose: out[C,R] = in[R,C]^T -------------------------
__global__ __launch_bounds__(256) void transpose32(
    const float* __restrict__ in, float* __restrict__ out, int R, int C)
{
    __shared__ float tile[32][33];
    const size_t eoff = (size_t)blockIdx.z * R * C;
    in += eoff; out += eoff;
    const int c0 = blockIdx.x * 32, r0 = blockIdx.y * 32;
    const int x = threadIdx.x & 31, y = threadIdx.x >> 5;
    #pragma unroll
    for (int j = 0; j < 32; j += 8)
        tile[y + j][x] = in[(size_t)(r0 + y + j) * C + c0 + x];
    __syncthreads();
    #pragma unroll
    for (int j = 0; j < 32; j += 8)
        out[(size_t)(c0 + y + j) * R + r0 + x] = tile[x][y + j];
}

// ---------------- block reduction helper -----------------------------------------
__device__ __forceinline__ float block_sum256(float v, float* red) {
    #pragma unroll
    for (int o = 16; o > 0; o >>= 1) v += __shfl_xor_sync(0xffffffffu, v, o);
    if ((threadIdx.x & 31) == 0) red[threadIdx.x >> 5] = v;
    __syncthreads();
    float s = red[0];
    #pragma unroll
    for (int i = 1; i < 8; i++) s += red[i];
    __syncthreads();
    return s;
}

// ---------------- attention: scores ----------------------------------------------
__global__ __launch_bounds__(256) void attn_scores(
    const float* __restrict__ q, const float* __restrict__ k, float* __restrict__ scr)
{
    __shared__ float Qs[64][68];
    __shared__ float Ks[64][68];
    const int t = threadIdx.x;
    const int tx = t & 15, ty = t >> 4;
    const int k0 = blockIdx.x * 64, q0 = blockIdx.y * 64;
    const int bh = blockIdx.z, b = bh >> 4, h = bh & 15;
    const size_t qbase = (size_t)(b*Sseq + q0) * Dm + h*64;
    const size_t kbase = (size_t)(b*Sseq + k0) * Dm + h*64;
    #pragma unroll
    for (int i = 0; i < 4; i++) {
        int f = t + 256*i;
        int row = f >> 4, c4 = (f & 15) * 4;
        float4 qv = *(const float4*)(q + qbase + (size_t)row*Dm + c4);
        float4 kv = *(const float4*)(k + kbase + (size_t)row*Dm + c4);
        Qs[c4+0][row]=qv.x; Qs[c4+1][row]=qv.y; Qs[c4+2][row]=qv.z; Qs[c4+3][row]=qv.w;
        Ks[c4+0][row]=kv.x; Ks[c4+1][row]=kv.y; Ks[c4+2][row]=kv.z; Ks[c4+3][row]=kv.w;
    }
    __syncthreads();
    float acc[4][4] = {};
    #pragma unroll 8
    for (int dh = 0; dh < 64; dh++) {
        float4 a  = *(const float4*)&Qs[dh][ty*4];
        float4 bv = *(const float4*)&Ks[dh][tx*4];
        float aa[4] = {a.x,a.y,a.z,a.w}, bbv[4] = {bv.x,bv.y,bv.z,bv.w};
        #pragma unroll
        for (int i = 0; i < 4; i++)
            #pragma unroll
            for (int j = 0; j < 4; j++)
                acc[i][j] = fmaf(aa[i], bbv[j], acc[i][j]);
    }
    const float scale = 0.125f;
    size_t obase = (size_t)bh*Sseq*Sseq + (size_t)q0*Sseq + k0;
    #pragma unroll
    for (int i = 0; i < 4; i++) {
        float4 o = make_float4(acc[i][0]*scale, acc[i][1]*scale, acc[i][2]*scale, acc[i][3]*scale);
        *(float4*)(scr + obase + (size_t)(ty*4+i)*Sseq + tx*4) = o;
    }
}

// ---------------- row softmax ----------------------------------------------------
__global__ __launch_bounds__(256) void softmax_rows(float* __restrict__ scr)
{
    __shared__ float red[8];
    const int t = threadIdx.x;
    float4* row = (float4*)(scr + (size_t)blockIdx.x * 1024);
    float4 v = row[t];
    float m = fmaxf(fmaxf(v.x, v.y), fmaxf(v.z, v.w));
    #pragma unroll
    for (int o = 16; o > 0; o >>= 1) m = fmaxf(m, __shfl_xor_sync(0xffffffffu, m, o));
    if ((t & 31) == 0) red[t >> 5] = m;
    __syncthreads();
    float mm = red[0];
    #pragma unroll
    for (int i = 1; i < 8; i++) mm = fmaxf(mm, red[i]);
    __syncthreads();
    v.x = __expf(v.x - mm); v.y = __expf(v.y - mm);
    v.z = __expf(v.z - mm); v.w = __expf(v.w - mm);
    float s = v.x + v.y + v.z + v.w;
    #pragma unroll
    for (int o = 16; o > 0; o >>= 1) s += __shfl_xor_sync(0xffffffffu, s, o);
    if ((t & 31) == 0) red[t >> 5] = s;
    __syncthreads();
    float ss = red[0];
    #pragma unroll
    for (int i = 1; i < 8; i++) ss += red[i];
    float inv = 1.f / ss;
    v.x *= inv; v.y *= inv; v.z *= inv; v.w *= inv;
    row[t] = v;
}

// ---------------- PV -------------------------------------------------------------
__global__ __launch_bounds__(256) void attn_pv(
    const float* __restrict__ scr, const float* __restrict__ v, float* __restrict__ out)
{
    __shared__ float Ps[64][68];
    __shared__ float Vs[64][68];
    const int t = threadIdx.x;
    const int tx = t & 15, ty = t >> 4;
    const int q0 = blockIdx.x * 64;
    const int bh = blockIdx.y, b = bh >> 4, h = bh & 15;
    float acc[4][4] = {};
    for (int kt = 0; kt < 16; kt++) {
        #pragma unroll
        for (int i = 0; i < 4; i++) {
            int f = t + 256*i;
            int r = f >> 4, c4 = (f & 15) * 4;
            float4 pv = *(const float4*)(scr + (size_t)bh*Sseq*Sseq + (size_t)(q0+r)*Sseq + kt*64 + c4);
            Ps[c4+0][r]=pv.x; Ps[c4+1][r]=pv.y; Ps[c4+2][r]=pv.z; Ps[c4+3][r]=pv.w;
            float4 vv = *(const float4*)(v + ((size_t)(b*Sseq) + kt*64 + r)*Dm + h*64 + c4);
            *(float4*)&Vs[r][c4] = vv;
        }
        __syncthreads();
        #pragma unroll 8
        for (int kk = 0; kk < 64; kk++) {
            float4 a  = *(const float4*)&Ps[kk][ty*4];
            float4 bv = *(const float4*)&Vs[kk][tx*4];
            float aa[4] = {a.x,a.y,a.z,a.w}, bbv[4] = {bv.x,bv.y,bv.z,bv.w};
            #pragma unroll
            for (int i = 0; i < 4; i++)
                #pragma unroll
                for (int j = 0; j < 4; j++)
                    acc[i][j] = fmaf(aa[i], bbv[j], acc[i][j]);
        }
        __syncthreads();
    }
    #pragma unroll
    for (int i = 0; i < 4; i++) {
        float4 o = make_float4(acc[i][0], acc[i][1], acc[i][2], acc[i][3]);
        *(float4*)(out + ((size_t)(b*Sseq) + q0 + ty*4 + i)*Dm + h*64 + tx*4) = o;
    }
}

// ---------------- residual add + layernorm ---------------------------------------
__global__ __launch_bounds__(256) void add_ln(
    const float* __restrict__ a, const float* __restrict__ b,
    const float* __restrict__ gamma, const float* __restrict__ beta,
    float* __restrict__ out)
{
    __shared__ float red[8];
    const int t = threadIdx.x;
    const size_t base = (size_t)blockIdx.x * Dm;
    float4 va = ((const float4*)(a + base))[t];
    float4 vb = ((const float4*)(b + base))[t];
    float4 s = make_float4(va.x+vb.x, va.y+vb.y, va.z+vb.z, va.w+vb.w);
    float tot = block_sum256(s.x + s.y + s.z + s.w, red);
    float mu = tot * (1.f / Dm);
    float lq = (s.x-mu)*(s.x-mu) + (s.y-mu)*(s.y-mu) + (s.z-mu)*(s.z-mu) + (s.w-mu)*(s.w-mu);
    float var = block_sum256(lq, red) * (1.f / Dm);
    float rstd = rsqrtf(var + EPSV);
    float4 gg = ((const float4*)gamma)[t];
    float4 bt = ((const float4*)beta)[t];
    float4 o;
    o.x = (s.x - mu) * rstd * gg.x + bt.x;
    o.y = (s.y - mu) * rstd * gg.y + bt.y;
    o.z = (s.z - mu) * rstd * gg.z + bt.z;
    o.w = (s.w - mu) * rstd * gg.w + bt.w;
    ((float4*)(out + base))[t] = o;
}

// ---------------- gate coefficients ----------------------------------------------
__global__ __launch_bounds__(256) void gate_coef(
    const float* __restrict__ xn, const float* __restrict__ gw, float* __restrict__ coef)
{
    __shared__ float red[16][9];
    const int t = threadIdx.x, tkn = blockIdx.x;
    float acc[16];
    #pragma unroll
    for (int ge = 0; ge < 16; ge++) acc[ge] = 0.f;
    for (int d = t; d < Dm; d += 256) {
        float xv = xn[(size_t)tkn*Dm + d];
        #pragma unroll
        for (int ge = 0; ge < 16; ge++)
            acc[ge] = fmaf(xv, gw[(size_t)(ge >> 3)*Dm*Ee + (size_t)d*Ee + (ge & 7)], acc[ge]);
    }
    #pragma unroll
    for (int ge = 0; ge < 16; ge++) {
        float v = acc[ge];
        #pragma unroll
        for (int o = 16; o > 0; o >>= 1) v += __shfl_xor_sync(0xffffffffu, v, o);
        if ((t & 31) == 0) red[ge][t >> 5] = v;
    }
    __syncthreads();
    if (t == 0) {
        float logits[16];
        #pragma unroll
        for (int ge = 0; ge < 16; ge++) {
            float s = 0.f;
            #pragma unroll
            for (int w2 = 0; w2 < 8; w2++) s += red[ge][w2];
            logits[ge] = s;
        }
        float c[8];
        #pragma unroll
        for (int e2 = 0; e2 < 8; e2++) c[e2] = 0.f;
        #pragma unroll
        for (int g = 0; g < 2; g++) {
            float m = logits[g*8];
            #pragma unroll
            for (int e2 = 1; e2 < 8; e2++) m = fmaxf(m, logits[g*8+e2]);
            float s = 0.f, pe[8];
            #pragma unroll
            for (int e2 = 0; e2 < 8; e2++) { pe[e2] = __expf(logits[g*8+e2] - m); s += pe[e2]; }
            float inv = 1.f / s;
            #pragma unroll
            for (int e2 = 0; e2 < 8; e2++) c[e2] += pe[e2] * inv;
        }
        #pragma unroll
        for (int e2 = 0; e2 < 8; e2++) coef[(size_t)tkn*8 + e2] = c[e2] * 0.5f;
    }
}

// ---------------- combine + residual + LN2 ---------------------------------------
__global__ __launch_bounds__(256) void combine_ln(
    const float* __restrict__ eo, const float* __restrict__ coef,
    const float* __restrict__ xn,
    const float* __restrict__ gamma, const float* __restrict__ beta,
    float* __restrict__ out)
{
    __shared__ float red[8];
    __shared__ float cf[8];
    const int t = threadIdx.x, tkn = blockIdx.x;
    if (t < 8) cf[t] = coef[(size_t)tkn*8 + t];
    __syncthreads();
    const size_t base = (size_t)tkn * Dm;
    float4 s = ((const float4*)(xn + base))[t];
    #pragma unroll
    for (int e2 = 0; e2 < 8; e2++) {
        float4 v = ((const float4*)(eo + ((size_t)e2*TOK + tkn)*Dm))[t];
        float c = cf[e2];
        s.x = fmaf(c, v.x, s.x); s.y = fmaf(c, v.y, s.y);
        s.z = fmaf(c, v.z, s.z); s.w = fmaf(c, v.w, s.w);
    }
    float tot = block_sum256(s.x + s.y + s.z + s.w, red);
    float mu = tot * (1.f / Dm);
    float lq = (s.x-mu)*(s.x-mu) + (s.y-mu)*(s.y-mu) + (s.z-mu)*(s.z-mu) + (s.w-mu)*(s.w-mu);
    float var = block_sum256(lq, red) * (1.f / Dm);
    float rstd = rsqrtf(var + EPSV);
    float4 gg = ((const float4*)gamma)[t];
    float4 bt = ((const float4*)beta)[t];
    float4 o;
    o.x = (s.x - mu) * rstd * gg.x + bt.x;
    o.y = (s.y - mu) * rstd * gg.y + bt.y;
    o.z = (s.z - mu) * rstd * gg.z + bt.z;
    o.w = (s.w - mu) * rstd * gg.w + bt.w;
    ((float4*)(out + base))[t] = o;
}

// ---------------- launch ----------------------------------------------------------
extern "C" void kernel_launch(void* const* d_in, const int* in_sizes, int n_in,
                              void* d_out, int out_size)
{
    const float* x     = (const float*)d_in[0];
    const float* wq    = (const float*)d_in[1];
    const float* bq    = (const float*)d_in[2];
    const float* wk    = (const float*)d_in[3];
    const float* bk    = (const float*)d_in[4];
    const float* wv    = (const float*)d_in[5];
    const float* bv    = (const float*)d_in[6];
    const float* wo    = (const float*)d_in[7];
    const float* bo    = (const float*)d_in[8];
    const float* ln1g  = (const float*)d_in[9];
    const float* ln1b  = (const float*)d_in[10];
    const float* ln2g  = (const float*)d_in[11];
    const float* ln2b  = (const float*)d_in[12];
    const float* gatew = (const float*)d_in[13];
    const float* ew1   = (const float*)d_in[14];
    const float* eb1   = (const float*)d_in[15];
    const float* ew2   = (const float*)d_in[16];
    const float* eb2   = (const float*)d_in[17];
    float* out = (float*)d_out;

    float *q, *k, *v, *attn, *proj, *normed, *scores, *h, *eo, *coef;
    float *wqt, *wkt, *wvt, *wot, *w1t, *w2t;
    cudaGetSymbolAddress((void**)&q,      g_q);
    cudaGetSymbolAddress((void**)&k,      g_k);
    cudaGetSymbolAddress((void**)&v,      g_v);
    cudaGetSymbolAddress((void**)&attn,   g_attn);
    cudaGetSymbolAddress((void**)&proj,   g_proj);
    cudaGetSymbolAddress((void**)&normed, g_normed);
    cudaGetSymbolAddress((void**)&scores, g_scores);
    cudaGetSymbolAddress((void**)&h,      g_h);
    cudaGetSymbolAddress((void**)&eo,     g_eo);
    cudaGetSymbolAddress((void**)&coef,   g_coef);
    cudaGetSymbolAddress((void**)&wqt,    g_wqt);
    cudaGetSymbolAddress((void**)&wkt,    g_wkt);
    cudaGetSymbolAddress((void**)&wvt,    g_wvt);
    cudaGetSymbolAddress((void**)&wot,    g_wot);
    cudaGetSymbolAddress((void**)&w1t,    g_w1t);
    cudaGetSymbolAddress((void**)&w2t,    g_w2t);

    cudaFuncSetAttribute(mma_gemm<false>, cudaFuncAttributeMaxDynamicSharedMemorySize, SMEM_GEMM_BYTES);
    cudaFuncSetAttribute(mma_gemm<true>,  cudaFuncAttributeMaxDynamicSharedMemorySize, SMEM_GEMM_BYTES);

    dim3 blk(256);

    // weight transposes (Wt[n][k] = W[k][n])
    transpose32<<<dim3(32, 32, 1), blk>>>(wq, wqt, Dm, Dm);
    transpose32<<<dim3(32, 32, 1), blk>>>(wk, wkt, Dm, Dm);
    transpose32<<<dim3(32, 32, 1), blk>>>(wv, wvt, Dm, Dm);
    transpose32<<<dim3(32, 32, 1), blk>>>(wo, wot, Dm, Dm);
    transpose32<<<dim3(Vv/32, Dm/32, Ee), blk>>>(ew1, w1t, Dm, Vv);
    transpose32<<<dim3(Dm/32, Vv/32, Ee), blk>>>(ew2, w2t, Vv, Dm);

    // QKV projections (tensor-core tf32)
    mma_gemm<false><<<dim3(8, 16, 1), blk, SMEM_GEMM_BYTES>>>(x, wqt, bq, q, TOK, Dm, Dm, 0, 0, 0, 0);
    mma_gemm<false><<<dim3(8, 16, 1), blk, SMEM_GEMM_BYTES>>>(x, wkt, bk, k, TOK, Dm, Dm, 0, 0, 0, 0);
    mma_gemm<false><<<dim3(8, 16, 1), blk, SMEM_GEMM_BYTES>>>(x, wvt, bv, v, TOK, Dm, Dm, 0, 0, 0, 0);

    // attention
    attn_scores<<<dim3(16, 16, 32), blk>>>(q, k, scores);
    softmax_rows<<<Bb*Hh*Sseq, blk>>>(scores);
    attn_pv<<<dim3(16, 32), blk>>>(scores, v, attn);

    // output projection + residual + LN1
    mma_gemm<false><<<dim3(8, 16, 1), blk, SMEM_GEMM_BYTES>>>(attn, wot, bo, proj, TOK, Dm, Dm, 0, 0, 0, 0);
    add_ln<<<TOK, blk>>>(proj, x, ln1g, ln1b, normed);

    // MoE
    gate_coef<<<TOK, blk>>>(normed, gatew, coef);
    mma_gemm<true><<<dim3(32, 16, Ee), blk, SMEM_GEMM_BYTES>>>(
        normed, w1t, eb1, h, TOK, Vv, Dm,
        0, (long long)Vv*Dm, (long long)Vv, (long long)TOK*Vv);
    mma_gemm<false><<<dim3(8, 16, Ee), blk, SMEM_GEMM_BYTES>>>(
        h, w2t, eb2, eo, TOK, Dm, Vv,
        (long long)TOK*Vv, (long long)Dm*Vv, (long long)Dm, (long long)TOK*Dm);

    // combine + residual + LN2
    combine_ln<<<TOK, blk>>>(eo, coef, normed, ln2g, ln2b, out);
}

// round 5
// speedup vs baseline: 6.3956x; 1.1122x over previous
#include <cuda_runtime.h>
#include <math.h>
#include <stdint.h>

// Problem dims
#define Dm   1024
#define Sseq 1024
#define Bb   2
#define Hh   16
#define Ee   8
#define Vv   4096
#define TOK  (Bb*Sseq)
#define EPSV 1e-5f

// ---------------- device scratch ------------------------------------------------
__device__ float g_q[TOK*Dm];
__device__ float g_k[TOK*Dm];
__device__ float g_v[TOK*Dm];
__device__ float g_attn[TOK*Dm];
__device__ float g_proj[TOK*Dm];
__device__ float g_normed[TOK*Dm];
__device__ float g_h[(size_t)Ee*TOK*Vv];
__device__ float g_eo[(size_t)Ee*TOK*Dm];
__device__ float g_coef[TOK*Ee];
// transposed weights (N-major: Wt[n][k])
__device__ float g_wqt[Dm*Dm];
__device__ float g_wkt[Dm*Dm];
__device__ float g_wvt[Dm*Dm];
__device__ float g_wot[Dm*Dm];
__device__ float g_w1t[(size_t)Ee*Vv*Dm];
__device__ float g_w2t[(size_t)Ee*Dm*Vv];

// ---------------- helpers -------------------------------------------------------
__device__ __forceinline__ uint32_t f2tf(float f) {
    uint32_t u; asm("cvt.rna.tf32.f32 %0, %1;" : "=r"(u) : "f"(f)); return u;
}
__device__ __forceinline__ void mma_tf32(float* c, const uint32_t* a, const uint32_t* b) {
    asm volatile("mma.sync.aligned.m16n8k8.row.col.f32.tf32.tf32.f32 "
        "{%0,%1,%2,%3}, {%4,%5,%6,%7}, {%8,%9}, {%0,%1,%2,%3};"
        : "+f"(c[0]), "+f"(c[1]), "+f"(c[2]), "+f"(c[3])
        : "r"(a[0]), "r"(a[1]), "r"(a[2]), "r"(a[3]), "r"(b[0]), "r"(b[1]));
}

// SMEM geometry for mma_gemm: padded stride 36 words per 32-float row.
#define LDS_STRIDE 36
#define TILE_WORDS (128 * LDS_STRIDE)            // 4608 words per buffer
#define SMEM_GEMM_BYTES (4 * TILE_WORDS * 4 * 2) // A(2 bufs) + B(2 bufs) = 73728

// ---------------- tensor-core tf32 GEMM: C[M,N] = A[M,K] @ Bt[N,K]^T + bias -----
template<bool RELU>
__global__ __launch_bounds__(256) void mma_gemm(
    const float* __restrict__ A, const float* __restrict__ Bt,
    const float* __restrict__ bias, float* __restrict__ C,
    int M, int N, int K,
    long long sA, long long sB, long long sBias, long long sC)
{
    extern __shared__ uint32_t sh[];
    uint32_t* Asm = sh;                    // [2][TILE_WORDS]
    uint32_t* Bsm = sh + 2 * TILE_WORDS;   // [2][TILE_WORDS]

    const int t = threadIdx.x;
    const int lane = t & 31, w = t >> 5;
    const int warp_m = w >> 2;
    const int warp_n = w & 3;
    const int lr = lane >> 2;
    const int lc = lane & 3;

    const int eb = blockIdx.z;
    A    += (size_t)eb * sA;
    Bt   += (size_t)eb * sB;
    bias += (size_t)eb * sBias;
    C    += (size_t)eb * sC;
    const int n0 = blockIdx.x * 128, m0 = blockIdx.y * 128;

    const int kc = (t & 7) * 4;
    const int r0 = t >> 3;
    const float* Ag = A  + (size_t)(m0 + r0) * K + kc;
    const float* Bg = Bt + (size_t)(n0 + r0) * K + kc;
    const int sts_base = r0 * LDS_STRIDE + kc;

    float acc[4][4][4];
    #pragma unroll
    for (int mt = 0; mt < 4; mt++)
        #pragma unroll
        for (int nt = 0; nt < 4; nt++)
            #pragma unroll
            for (int i = 0; i < 4; i++) acc[mt][nt][i] = 0.f;

    const int nst = K >> 5;

    {
        float4 pa[4], pb[4];
        #pragma unroll
        for (int i = 0; i < 4; i++) {
            pa[i] = *(const float4*)(Ag + (size_t)(32 * i) * K);
            pb[i] = *(const float4*)(Bg + (size_t)(32 * i) * K);
        }
        #pragma unroll
        for (int i = 0; i < 4; i++) {
            uint32_t* da = Asm + sts_base + i * 32 * LDS_STRIDE;
            uint32_t* db = Bsm + sts_base + i * 32 * LDS_STRIDE;
            da[0] = f2tf(pa[i].x); da[1] = f2tf(pa[i].y);
            da[2] = f2tf(pa[i].z); da[3] = f2tf(pa[i].w);
            db[0] = f2tf(pb[i].x); db[1] = f2tf(pb[i].y);
            db[2] = f2tf(pb[i].z); db[3] = f2tf(pb[i].w);
        }
    }
    __syncthreads();

    const int a_off = (warp_m * 64 + lr) * LDS_STRIDE + lc;
    const int b_off = (warp_n * 32 + lr) * LDS_STRIDE + lc;

    for (int s = 0; s < nst; s++) {
        const int buf = s & 1;
        const bool more = (s + 1) < nst;
        float4 pa[4], pb[4];
        if (more) {
            const float* ag = Ag + (size_t)(32 * (s + 1));
            const float* bg = Bg + (size_t)(32 * (s + 1));
            #pragma unroll
            for (int i = 0; i < 4; i++) {
                pa[i] = *(const float4*)(ag + (size_t)(32 * i) * K);
                pb[i] = *(const float4*)(bg + (size_t)(32 * i) * K);
            }
        }

        const uint32_t* Apt = Asm + buf * TILE_WORDS + a_off;
        const uint32_t* Bpt = Bsm + buf * TILE_WORDS + b_off;
        #pragma unroll
        for (int kk = 0; kk < 4; kk++) {
            const int k = kk * 8;
            uint32_t af[4][4], bf[4][2];
            #pragma unroll
            for (int mt = 0; mt < 4; mt++) {
                af[mt][0] = Apt[(mt * 16    ) * LDS_STRIDE + k];
                af[mt][1] = Apt[(mt * 16 + 8) * LDS_STRIDE + k];
                af[mt][2] = Apt[(mt * 16    ) * LDS_STRIDE + k + 4];
                af[mt][3] = Apt[(mt * 16 + 8) * LDS_STRIDE + k + 4];
            }
            #pragma unroll
            for (int nt = 0; nt < 4; nt++) {
                bf[nt][0] = Bpt[(nt * 8) * LDS_STRIDE + k];
                bf[nt][1] = Bpt[(nt * 8) * LDS_STRIDE + k + 4];
            }
            #pragma unroll
            for (int mt = 0; mt < 4; mt++)
                #pragma unroll
                for (int nt = 0; nt < 4; nt++)
                    mma_tf32(acc[mt][nt], af[mt], bf[nt]);
        }

        if (more) {
            const int nb = (s + 1) & 1;
            #pragma unroll
            for (int i = 0; i < 4; i++) {
                uint32_t* da = Asm + nb * TILE_WORDS + sts_base + i * 32 * LDS_STRIDE;
                uint32_t* db = Bsm + nb * TILE_WORDS + sts_base + i * 32 * LDS_STRIDE;
                da[0] = f2tf(pa[i].x); da[1] = f2tf(pa[i].y);
                da[2] = f2tf(pa[i].z); da[3] = f2tf(pa[i].w);
                db[0] = f2tf(pb[i].x); db[1] = f2tf(pb[i].y);
                db[2] = f2tf(pb[i].z); db[3] = f2tf(pb[i].w);
            }
        }
        __syncthreads();
    }

    #pragma unroll
    for (int mt = 0; mt < 4; mt++) {
        const int m = m0 + warp_m * 64 + mt * 16 + lr;
        #pragma unroll
        for (int nt = 0; nt < 4; nt++) {
            const int n = n0 + warp_n * 32 + nt * 8 + lc * 2;
            const float b0 = bias[n], b1 = bias[n + 1];
            float o0 = acc[mt][nt][0] + b0, o1 = acc[mt][nt][1] + b1;
            float o2 = acc[mt][nt][2] + b0, o3 = acc[mt][nt][3] + b1;
            if (RELU) {
                o0 = fmaxf(o0, 0.f); o1 = fmaxf(o1, 0.f);
                o2 = fmaxf(o2, 0.f); o3 = fmaxf(o3, 0.f);
            }
            *(float2*)(C + (size_t)m * N + n)       = make_float2(o0, o1);
            *(float2*)(C + (size_t)(m + 8) * N + n) = make_float2(o2, o3);
        }
    }
}

// ---------------- fused flash attention (tf32 mma) -------------------------------
// One CTA: 128 q-rows of one (b,h). Loop over 8 k-tiles of 128.
// smem float offsets:
#define FA_QS   0                  // [128][68]
#define FA_KS   8704               // [128][68]
#define FA_VS   17408              // [128][72]
#define FA_PS   26624              // [128][132]
#define FA_RED  43520              // [128][4]
#define FA_MS   44032              // [128]
#define FA_LS   44160              // [128]
#define FA_AL   44288              // [128]
#define FA_WORDS 44416
#define FA_BYTES (FA_WORDS * 4)    // 177664

__global__ __launch_bounds__(256) void fused_attn(
    const float* __restrict__ q, const float* __restrict__ k,
    const float* __restrict__ v, float* __restrict__ out)
{
    extern __shared__ float fsh[];
    uint32_t* Qs = (uint32_t*)(fsh + FA_QS);
    uint32_t* Ks = (uint32_t*)(fsh + FA_KS);
    uint32_t* Vs = (uint32_t*)(fsh + FA_VS);
    uint32_t* Ps = (uint32_t*)(fsh + FA_PS);
    float* red   = fsh + FA_RED;
    float* m_s   = fsh + FA_MS;
    float* l_s   = fsh + FA_LS;
    float* al_s  = fsh + FA_AL;

    const int t = threadIdx.x;
    const int lane = t & 31, w = t >> 5;
    const int warp_m = w >> 2;   // S-mma: 0..1
    const int warp_n = w & 3;    // S-mma: 0..3
    const int ow_m = w >> 1;     // PV-mma: 0..3
    const int ow_n = w & 1;      // PV-mma: 0..1
    const int lr = lane >> 2, lc = lane & 3;

    const int q0 = blockIdx.x * 128;
    const int bh = blockIdx.y, b = bh >> 4, h = bh & 15;
    const size_t qbase = (size_t)(b * Sseq + q0) * Dm + h * 64;
    const size_t kvbase = (size_t)(b * Sseq) * Dm + h * 64;

    // load Q tile (tf32)
    #pragma unroll
    for (int i = 0; i < 8; i++) {
        int idx = t + 256 * i;            // 2048 float4s
        int row = idx >> 4, c4 = (idx & 15) * 4;
        float4 qv = *(const float4*)(q + qbase + (size_t)row * Dm + c4);
        uint32_t* d = Qs + row * 68 + c4;
        d[0] = f2tf(qv.x); d[1] = f2tf(qv.y); d[2] = f2tf(qv.z); d[3] = f2tf(qv.w);
    }
    if (t < 128) { m_s[t] = -1e30f; l_s[t] = 0.f; }

    float acc_o[2][4][4];
    #pragma unroll
    for (int mt = 0; mt < 2; mt++)
        #pragma unroll
        for (int nt = 0; nt < 4; nt++)
            #pragma unroll
            for (int i = 0; i < 4; i++) acc_o[mt][nt][i] = 0.f;

    const int a_off = (warp_m * 64 + lr) * 68 + lc;
    const int b_off = (warp_n * 32 + lr) * 68 + lc;
    const int p_off = (ow_m * 32 + lr) * 132 + lc;

    for (int kt = 0; kt < 8; kt++) {
        // load K,V tiles (tf32)
        const size_t kb = kvbase + (size_t)(kt * 128) * Dm;
        #pragma unroll
        for (int i = 0; i < 8; i++) {
            int idx = t + 256 * i;
            int row = idx >> 4, c4 = (idx & 15) * 4;
            float4 kv = *(const float4*)(k + kb + (size_t)row * Dm + c4);
            float4 vv = *(const float4*)(v + kb + (size_t)row * Dm + c4);
            uint32_t* dk = Ks + row * 68 + c4;
            uint32_t* dv = Vs + row * 72 + c4;
            dk[0] = f2tf(kv.x); dk[1] = f2tf(kv.y); dk[2] = f2tf(kv.z); dk[3] = f2tf(kv.w);
            dv[0] = f2tf(vv.x); dv[1] = f2tf(vv.y); dv[2] = f2tf(vv.z); dv[3] = f2tf(vv.w);
        }
        __syncthreads();

        // S = Q @ K^T  (128x128, K-dim 64)
        float acc_s[4][4][4];
        #pragma unroll
        for (int mt = 0; mt < 4; mt++)
            #pragma unroll
            for (int nt = 0; nt < 4; nt++)
                #pragma unroll
                for (int i = 0; i < 4; i++) acc_s[mt][nt][i] = 0.f;
        #pragma unroll
        for (int kk = 0; kk < 8; kk++) {
            const int kx = kk * 8;
            uint32_t af[4][4], bf[4][2];
            #pragma unroll
            for (int mt = 0; mt < 4; mt++) {
                af[mt][0] = Qs[a_off + (mt * 16    ) * 68 + kx];
                af[mt][1] = Qs[a_off + (mt * 16 + 8) * 68 + kx];
                af[mt][2] = Qs[a_off + (mt * 16    ) * 68 + kx + 4];
                af[mt][3] = Qs[a_off + (mt * 16 + 8) * 68 + kx + 4];
            }
            #pragma unroll
            for (int nt = 0; nt < 4; nt++) {
                bf[nt][0] = Ks[b_off + (nt * 8) * 68 + kx];
                bf[nt][1] = Ks[b_off + (nt * 8) * 68 + kx + 4];
            }
            #pragma unroll
            for (int mt = 0; mt < 4; mt++)
                #pragma unroll
                for (int nt = 0; nt < 4; nt++)
                    mma_tf32(acc_s[mt][nt], af[mt], bf[nt]);
        }

        // row max over this tile (raw scores; scale by 0.125 later)
        #pragma unroll
        for (int mt = 0; mt < 4; mt++) {
            #pragma unroll
            for (int half = 0; half < 2; half++) {
                float pm = -1e30f;
                #pragma unroll
                for (int nt = 0; nt < 4; nt++) {
                    pm = fmaxf(pm, acc_s[mt][nt][half * 2]);
                    pm = fmaxf(pm, acc_s[mt][nt][half * 2 + 1]);
                }
                pm = fmaxf(pm, __shfl_xor_sync(0xffffffffu, pm, 1));
                pm = fmaxf(pm, __shfl_xor_sync(0xffffffffu, pm, 2));
                if (lc == 0)
                    red[(warp_m * 64 + mt * 16 + half * 8 + lr) * 4 + warp_n] = pm;
            }
        }
        __syncthreads();

        // per-row online-max update
        if (t < 128) {
            float tm = fmaxf(fmaxf(red[t * 4 + 0], red[t * 4 + 1]),
                             fmaxf(red[t * 4 + 2], red[t * 4 + 3])) * 0.125f;
            float mo = m_s[t];
            float mn = fmaxf(mo, tm);
            al_s[t] = __expf(mo - mn);
            m_s[t]  = mn;
        }
        __syncthreads();

        // P = exp(0.125*S - m), write to smem (tf32), row-sum partials
        #pragma unroll
        for (int mt = 0; mt < 4; mt++) {
            #pragma unroll
            for (int half = 0; half < 2; half++) {
                const int row = warp_m * 64 + mt * 16 + half * 8 + lr;
                const float mrow = m_s[row];
                float ps = 0.f;
                #pragma unroll
                for (int nt = 0; nt < 4; nt++) {
                    const int col = warp_n * 32 + nt * 8 + lc * 2;
                    float p0 = __expf(acc_s[mt][nt][half * 2]     * 0.125f - mrow);
                    float p1 = __expf(acc_s[mt][nt][half * 2 + 1] * 0.125f - mrow);
                    ps += p0 + p1;
                    Ps[row * 132 + col]     = f2tf(p0);
                    Ps[row * 132 + col + 1] = f2tf(p1);
                }
                ps += __shfl_xor_sync(0xffffffffu, ps, 1);
                ps += __shfl_xor_sync(0xffffffffu, ps, 2);
                if (lc == 0) red[row * 4 + warp_n] = ps;
            }
        }
        // scale O by alpha (alpha valid since last sync)
        #pragma unroll
        for (int mt = 0; mt < 2; mt++) {
            const int row0 = ow_m * 32 + mt * 16 + lr;
            const float a0 = al_s[row0], a1 = al_s[row0 + 8];
            #pragma unroll
            for (int nt = 0; nt < 4; nt++) {
                acc_o[mt][nt][0] *= a0; acc_o[mt][nt][1] *= a0;
                acc_o[mt][nt][2] *= a1; acc_o[mt][nt][3] *= a1;
            }
        }
        __syncthreads();

        if (t < 128)
            l_s[t] = l_s[t] * al_s[t]
                   + red[t * 4 + 0] + red[t * 4 + 1] + red[t * 4 + 2] + red[t * 4 + 3];

        // O += P @ V  (128x64, K-dim 128)
        #pragma unroll
        for (int kk = 0; kk < 16; kk++) {
            const int kx = kk * 8;
            uint32_t af[2][4], bf[4][2];
            #pragma unroll
            for (int mt = 0; mt < 2; mt++) {
                af[mt][0] = Ps[p_off + (mt * 16    ) * 132 + kx];
                af[mt][1] = Ps[p_off + (mt * 16 + 8) * 132 + kx];
                af[mt][2] = Ps[p_off + (mt * 16    ) * 132 + kx + 4];
                af[mt][3] = Ps[p_off + (mt * 16 + 8) * 132 + kx + 4];
            }
            #pragma unroll
            for (int nt = 0; nt < 4; nt++) {
                const int n = ow_n * 32 + nt * 8 + lr;
                bf[nt][0] = Vs[(kx + lc) * 72 + n];
                bf[nt][1] = Vs[(kx + lc + 4) * 72 + n];
            }
            #pragma unroll
            for (int mt = 0; mt < 2; mt++)
                #pragma unroll
                for (int nt = 0; nt < 4; nt++)
                    mma_tf32(acc_o[mt][nt], af[mt], bf[nt]);
        }
        __syncthreads();   // Ks/Vs/Ps/red free for next iter
    }

    // normalize + store O
    #pragma unroll
    for (int mt = 0; mt < 2; mt++) {
        const int row0 = ow_m * 32 + mt * 16 + lr;
        const float i0 = 1.f / l_s[row0], i1 = 1.f / l_s[row0 + 8];
        #pragma unroll
        for (int nt = 0; nt < 4; nt++) {
            const int col = ow_n * 32 + nt * 8 + lc * 2;
            float* o0 = out + (size_t)(b * Sseq + q0 + row0) * Dm + h * 64 + col;
            float* o1 = out + (size_t)(b * Sseq + q0 + row0 + 8) * Dm + h * 64 + col;
            *(float2*)o0 = make_float2(acc_o[mt][nt][0] * i0, acc_o[mt][nt][1] * i0);
            *(float2*)o1 = make_float2(acc_o[mt][nt][2] * i1, acc_o[mt][nt][3] * i1);
        }
    }
}

// ---------------- weight transpose: out[C,R] = in[R,C]^T -------------------------
__global__ __launch_bounds__(256) void transpose32(
    const float* __restrict__ in, float* __restrict__ out, int R, int C)
{
    __shared__ float tile[32][33];
    const size_t eoff = (size_t)blockIdx.z * R * C;
    in += eoff; out += eoff;
    const int c0 = blockIdx.x * 32, r0 = blockIdx.y * 32;
    const int x = threadIdx.x & 31, y = threadIdx.x >> 5;
    #pragma unroll
    for (int j = 0; j < 32; j += 8)
        tile[y + j][x] = in[(size_t)(r0 + y + j) * C + c0 + x];
    __syncthreads();
    #pragma unroll
    for (int j = 0; j < 32; j += 8)
        out[(size_t)(c0 + y + j) * R + r0 + x] = tile[x][y + j];
}

// ---------------- block reduction helper -----------------------------------------
__device__ __forceinline__ float block_sum256(float v, float* red) {
    #pragma unroll
    for (int o = 16; o > 0; o >>= 1) v += __shfl_xor_sync(0xffffffffu, v, o);
    if ((threadIdx.x & 31) == 0) red[threadIdx.x >> 5] = v;
    __syncthreads();
    float s = red[0];
    #pragma unroll
    for (int i = 1; i < 8; i++) s += red[i];
    __syncthreads();
    return s;
}

// ---------------- residual add + layernorm ---------------------------------------
__global__ __launch_bounds__(256) void add_ln(
    const float* __restrict__ a, const float* __restrict__ b,
    const float* __restrict__ gamma, const float* __restrict__ beta,
    float* __restrict__ out)
{
    __shared__ float red[8];
    const int t = threadIdx.x;
    const size_t base = (size_t)blockIdx.x * Dm;
    float4 va = ((const float4*)(a + base))[t];
    float4 vb = ((const float4*)(b + base))[t];
    float4 s = make_float4(va.x+vb.x, va.y+vb.y, va.z+vb.z, va.w+vb.w);
    float tot = block_sum256(s.x + s.y + s.z + s.w, red);
    float mu = tot * (1.f / Dm);
    float lq = (s.x-mu)*(s.x-mu) + (s.y-mu)*(s.y-mu) + (s.z-mu)*(s.z-mu) + (s.w-mu)*(s.w-mu);
    float var = block_sum256(lq, red) * (1.f / Dm);
    float rstd = rsqrtf(var + EPSV);
    float4 gg = ((const float4*)gamma)[t];
    float4 bt = ((const float4*)beta)[t];
    float4 o;
    o.x = (s.x - mu) * rstd * gg.x + bt.x;
    o.y = (s.y - mu) * rstd * gg.y + bt.y;
    o.z = (s.z - mu) * rstd * gg.z + bt.z;
    o.w = (s.w - mu) * rstd * gg.w + bt.w;
    ((float4*)(out + base))[t] = o;
}

// ---------------- gate coefficients ----------------------------------------------
__global__ __launch_bounds__(256) void gate_coef(
    const float* __restrict__ xn, const float* __restrict__ gw, float* __restrict__ coef)
{
    __shared__ float red[16][9];
    const int t = threadIdx.x, tkn = blockIdx.x;
    float acc[16];
    #pragma unroll
    for (int ge = 0; ge < 16; ge++) acc[ge] = 0.f;
    for (int d = t; d < Dm; d += 256) {
        float xv = xn[(size_t)tkn*Dm + d];
        #pragma unroll
        for (int ge = 0; ge < 16; ge++)
            acc[ge] = fmaf(xv, gw[(size_t)(ge >> 3)*Dm*Ee + (size_t)d*Ee + (ge & 7)], acc[ge]);
    }
    #pragma unroll
    for (int ge = 0; ge < 16; ge++) {
        float v = acc[ge];
        #pragma unroll
        for (int o = 16; o > 0; o >>= 1) v += __shfl_xor_sync(0xffffffffu, v, o);
        if ((t & 31) == 0) red[ge][t >> 5] = v;
    }
    __syncthreads();
    if (t == 0) {
        float logits[16];
        #pragma unroll
        for (int ge = 0; ge < 16; ge++) {
            float s = 0.f;
            #pragma unroll
            for (int w2 = 0; w2 < 8; w2++) s += red[ge][w2];
            logits[ge] = s;
        }
        float c[8];
        #pragma unroll
        for (int e2 = 0; e2 < 8; e2++) c[e2] = 0.f;
        #pragma unroll
        for (int g = 0; g < 2; g++) {
            float m = logits[g*8];
            #pragma unroll
            for (int e2 = 1; e2 < 8; e2++) m = fmaxf(m, logits[g*8+e2]);
            float s = 0.f, pe[8];
            #pragma unroll
            for (int e2 = 0; e2 < 8; e2++) { pe[e2] = __expf(logits[g*8+e2] - m); s += pe[e2]; }
            float inv = 1.f / s;
            #pragma unroll
            for (int e2 = 0; e2 < 8; e2++) c[e2] += pe[e2] * inv;
        }
        #pragma unroll
        for (int e2 = 0; e2 < 8; e2++) coef[(size_t)tkn*8 + e2] = c[e2] * 0.5f;
    }
}

// ---------------- combine + residual + LN2 ---------------------------------------
__global__ __launch_bounds__(256) void combine_ln(
    const float* __restrict__ eo, const float* __restrict__ coef,
    const float* __restrict__ xn,
    const float* __restrict__ gamma, const float* __restrict__ beta,
    float* __restrict__ out)
{
    __shared__ float red[8];
    __shared__ float cf[8];
    const int t = threadIdx.x, tkn = blockIdx.x;
    if (t < 8) cf[t] = coef[(size_t)tkn*8 + t];
    __syncthreads();
    const size_t base = (size_t)tkn * Dm;
    float4 s = ((const float4*)(xn + base))[t];
    #pragma unroll
    for (int e2 = 0; e2 < 8; e2++) {
        float4 v = ((const float4*)(eo + ((size_t)e2*TOK + tkn)*Dm))[t];
        float c = cf[e2];
        s.x = fmaf(c, v.x, s.x); s.y = fmaf(c, v.y, s.y);
        s.z = fmaf(c, v.z, s.z); s.w = fmaf(c, v.w, s.w);
    }
    float tot = block_sum256(s.x + s.y + s.z + s.w, red);
    float mu = tot * (1.f / Dm);
    float lq = (s.x-mu)*(s.x-mu) + (s.y-mu)*(s.y-mu) + (s.z-mu)*(s.z-mu) + (s.w-mu)*(s.w-mu);
    float var = block_sum256(lq, red) * (1.f / Dm);
    float rstd = rsqrtf(var + EPSV);
    float4 gg = ((const float4*)gamma)[t];
    float4 bt = ((const float4*)beta)[t];
    float4 o;
    o.x = (s.x - mu) * rstd * gg.x + bt.x;
    o.y = (s.y - mu) * rstd * gg.y + bt.y;
    o.z = (s.z - mu) * rstd * gg.z + bt.z;
    o.w = (s.w - mu) * rstd * gg.w + bt.w;
    ((float4*)(out + base))[t] = o;
}

// ---------------- launch ----------------------------------------------------------
extern "C" void kernel_launch(void* const* d_in, const int* in_sizes, int n_in,
                              void* d_out, int out_size)
{
    const float* x     = (const float*)d_in[0];
    const float* wq    = (const float*)d_in[1];
    const float* bq    = (const float*)d_in[2];
    const float* wk    = (const float*)d_in[3];
    const float* bk    = (const float*)d_in[4];
    const float* wv    = (const float*)d_in[5];
    const float* bv    = (const float*)d_in[6];
    const float* wo    = (const float*)d_in[7];
    const float* bo    = (const float*)d_in[8];
    const float* ln1g  = (const float*)d_in[9];
    const float* ln1b  = (const float*)d_in[10];
    const float* ln2g  = (const float*)d_in[11];
    const float* ln2b  = (const float*)d_in[12];
    const float* gatew = (const float*)d_in[13];
    const float* ew1   = (const float*)d_in[14];
    const float* eb1   = (const float*)d_in[15];
    const float* ew2   = (const float*)d_in[16];
    const float* eb2   = (const float*)d_in[17];
    float* out = (float*)d_out;

    float *q, *k, *v, *attn, *proj, *normed, *h, *eo, *coef;
    float *wqt, *wkt, *wvt, *wot, *w1t, *w2t;
    cudaGetSymbolAddress((void**)&q,      g_q);
    cudaGetSymbolAddress((void**)&k,      g_k);
    cudaGetSymbolAddress((void**)&v,      g_v);
    cudaGetSymbolAddress((void**)&attn,   g_attn);
    cudaGetSymbolAddress((void**)&proj,   g_proj);
    cudaGetSymbolAddress((void**)&normed, g_normed);
    cudaGetSymbolAddress((void**)&h,      g_h);
    cudaGetSymbolAddress((void**)&eo,     g_eo);
    cudaGetSymbolAddress((void**)&coef,   g_coef);
    cudaGetSymbolAddress((void**)&wqt,    g_wqt);
    cudaGetSymbolAddress((void**)&wkt,    g_wkt);
    cudaGetSymbolAddress((void**)&wvt,    g_wvt);
    cudaGetSymbolAddress((void**)&wot,    g_wot);
    cudaGetSymbolAddress((void**)&w1t,    g_w1t);
    cudaGetSymbolAddress((void**)&w2t,    g_w2t);

    cudaFuncSetAttribute(mma_gemm<false>, cudaFuncAttributeMaxDynamicSharedMemorySize, SMEM_GEMM_BYTES);
    cudaFuncSetAttribute(mma_gemm<true>,  cudaFuncAttributeMaxDynamicSharedMemorySize, SMEM_GEMM_BYTES);
    cudaFuncSetAttribute(fused_attn,      cudaFuncAttributeMaxDynamicSharedMemorySize, FA_BYTES);

    dim3 blk(256);

    // weight transposes (Wt[n][k] = W[k][n])
    transpose32<<<dim3(32, 32, 1), blk>>>(wq, wqt, Dm, Dm);
    transpose32<<<dim3(32, 32, 1), blk>>>(wk, wkt, Dm, Dm);
    transpose32<<<dim3(32, 32, 1), blk>>>(wv, wvt, Dm, Dm);
    transpose32<<<dim3(32, 32, 1), blk>>>(wo, wot, Dm, Dm);
    transpose32<<<dim3(Vv/32, Dm/32, Ee), blk>>>(ew1, w1t, Dm, Vv);
    transpose32<<<dim3(Dm/32, Vv/32, Ee), blk>>>(ew2, w2t, Vv, Dm);

    // QKV projections (tensor-core tf32)
    mma_gemm<false><<<dim3(8, 16, 1), blk, SMEM_GEMM_BYTES>>>(x, wqt, bq, q, TOK, Dm, Dm, 0, 0, 0, 0);
    mma_gemm<false><<<dim3(8, 16, 1), blk, SMEM_GEMM_BYTES>>>(x, wkt, bk, k, TOK, Dm, Dm, 0, 0, 0, 0);
    mma_gemm<false><<<dim3(8, 16, 1), blk, SMEM_GEMM_BYTES>>>(x, wvt, bv, v, TOK, Dm, Dm, 0, 0, 0, 0);

    // fused flash attention
    fused_attn<<<dim3(8, 32), blk, FA_BYTES>>>(q, k, v, attn);

    // output projection + residual + LN1
    mma_gemm<false><<<dim3(8, 16, 1), blk, SMEM_GEMM_BYTES>>>(attn, wot, bo, proj, TOK, Dm, Dm, 0, 0, 0, 0);
    add_ln<<<TOK, blk>>>(proj, x, ln1g, ln1b, normed);

    // MoE
    gate_coef<<<TOK, blk>>>(normed, gatew, coef);
    mma_gemm<true><<<dim3(32, 16, Ee), blk, SMEM_GEMM_BYTES>>>(
        normed, w1t, eb1, h, TOK, Vv, Dm,
        0, (long long)Vv*Dm, (long long)Vv, (long long)TOK*Vv);
    mma_gemm<false><<<dim3(8, 16, Ee), blk, SMEM_GEMM_BYTES>>>(
        h, w2t, eb2, eo, TOK, Dm, Vv,
        (long long)TOK*Vv, (long long)Dm*Vv, (long long)Dm, (long long)TOK*Dm);

    // combine + residual + LN2
    combine_ln<<<TOK, blk>>>(eo, coef, normed, ln2g, ln2b, out);
}